// round 3
// baseline (speedup 1.0000x reference)
#include <cuda_runtime.h>
#include <math.h>

// Problem constants
#define NB     4
#define NSEQ   1024
#define DMODEL 512
#define NH     8
#define HD     64
#define EOUT   2048          // 2*H*Dv + 2*H*Dq
#define ROWS   (NB*NSEQ)     // 4096

// Scratch (allocation-free requirement -> __device__ globals)
__device__ float g_nx[ROWS*DMODEL];   // LN(x)
__device__ float g_uo[ROWS*EOUT];     // silu(nx @ uvqk): [u|v|q|k]
__device__ float g_ao[ROWS*DMODEL];   // attention output
__device__ float g_t [ROWS*DMODEL];   // u * LN(ao)

// ---------------------------------------------------------------------------
// Block reduction (256 threads)
// ---------------------------------------------------------------------------
__device__ __forceinline__ float blk_reduce_sum(float v, float* sm) {
    int tid = threadIdx.x;
    #pragma unroll
    for (int o = 16; o > 0; o >>= 1) v += __shfl_down_sync(0xffffffffu, v, o);
    if ((tid & 31) == 0) sm[tid >> 5] = v;
    __syncthreads();
    if (tid < 32) {
        float t = (tid < 8) ? sm[tid] : 0.0f;
        #pragma unroll
        for (int o = 4; o > 0; o >>= 1) t += __shfl_down_sync(0xffffffffu, t, o);
        if (tid == 0) sm[0] = t;
    }
    __syncthreads();
    float r = sm[0];
    __syncthreads();
    return r;
}

// ---------------------------------------------------------------------------
// Kernel 1: LayerNorm(x) -> g_nx          grid=4096, block=256
// ---------------------------------------------------------------------------
__global__ void ln_x_kernel(const float* __restrict__ x,
                            const float* __restrict__ w,
                            const float* __restrict__ b) {
    __shared__ float sm[8];
    int r = blockIdx.x, tid = threadIdx.x;
    const float* xr = x + (size_t)r * DMODEL;
    float v0 = xr[tid], v1 = xr[tid + 256];
    float mean = blk_reduce_sum(v0 + v1, sm) * (1.0f / DMODEL);
    float d0 = v0 - mean, d1 = v1 - mean;
    float var = blk_reduce_sum(d0*d0 + d1*d1, sm) * (1.0f / DMODEL);
    float inv = rsqrtf(var + 1e-5f);
    g_nx[(size_t)r*DMODEL + tid]       = d0*inv*w[tid]       + b[tid];
    g_nx[(size_t)r*DMODEL + tid + 256] = d1*inv*w[tid + 256] + b[tid + 256];
}

// ---------------------------------------------------------------------------
// Kernel 4: t = u * LayerNorm(ao)          grid=4096, block=256
// ---------------------------------------------------------------------------
__global__ void ln_a_kernel(const float* __restrict__ w,
                            const float* __restrict__ b) {
    __shared__ float sm[8];
    int r = blockIdx.x, tid = threadIdx.x;
    const float* ar = g_ao + (size_t)r * DMODEL;
    float v0 = ar[tid], v1 = ar[tid + 256];
    float mean = blk_reduce_sum(v0 + v1, sm) * (1.0f / DMODEL);
    float d0 = v0 - mean, d1 = v1 - mean;
    float var = blk_reduce_sum(d0*d0 + d1*d1, sm) * (1.0f / DMODEL);
    float inv = rsqrtf(var + 1e-5f);
    const float* ur = g_uo + (size_t)r * EOUT;   // u = first 512 cols
    g_t[(size_t)r*DMODEL + tid]       = (d0*inv*w[tid]       + b[tid])       * ur[tid];
    g_t[(size_t)r*DMODEL + tid + 256] = (d1*inv*w[tid + 256] + b[tid + 256]) * ur[tid + 256];
}

// ---------------------------------------------------------------------------
// fp32 SMEM-tiled GEMM: C[M,N] = A[M,K] @ B[K,N]
// Tile 128x64x16, 256 threads, 8x4 microtile.
// EPI 0: silu epilogue.   EPI 1: + bias[c] + resid[r,c], zero if pm[r].
// ---------------------------------------------------------------------------
template<int EPI>
__global__ void gemm_kernel(const float* __restrict__ A,
                            const float* __restrict__ Bm,
                            float* __restrict__ C,
                            int M, int N, int K,
                            const float* __restrict__ bias,
                            const float* __restrict__ resid,
                            const unsigned char* __restrict__ pm) {
    __shared__ float As[128][16];
    __shared__ float Bs[16][64];
    int tid = threadIdx.x;
    int bm = blockIdx.y * 128, bn = blockIdx.x * 64;
    int tx = tid & 15, ty = tid >> 4;

    float acc[8][4];
    #pragma unroll
    for (int i = 0; i < 8; i++)
        #pragma unroll
        for (int j = 0; j < 4; j++) acc[i][j] = 0.0f;

    for (int k0 = 0; k0 < K; k0 += 16) {
        // load A tile: 512 float4s, 2 per thread
        #pragma unroll
        for (int i = 0; i < 2; i++) {
            int f = tid*2 + i, r = f >> 2, c = (f & 3) << 2;
            *(float4*)&As[r][c] = *(const float4*)&A[(size_t)(bm + r)*K + k0 + c];
        }
        // load B tile: 256 float4s, 1 per thread
        {
            int r = tid >> 4, c = (tid & 15) << 2;
            *(float4*)&Bs[r][c] = *(const float4*)&Bm[(size_t)(k0 + r)*N + bn + c];
        }
        __syncthreads();
        #pragma unroll
        for (int kk = 0; kk < 16; kk++) {
            float4 rb = *(float4*)&Bs[kk][tx*4];
            #pragma unroll
            for (int i = 0; i < 8; i++) {
                float ra = As[ty*8 + i][kk];
                acc[i][0] += ra * rb.x;
                acc[i][1] += ra * rb.y;
                acc[i][2] += ra * rb.z;
                acc[i][3] += ra * rb.w;
            }
        }
        __syncthreads();
    }

    #pragma unroll
    for (int i = 0; i < 8; i++) {
        int r = bm + ty*8 + i;
        #pragma unroll
        for (int j = 0; j < 4; j++) {
            int c = bn + tx*4 + j;
            float v = acc[i][j];
            if (EPI == 0) {
                v = v / (1.0f + expf(-v));          // silu
            } else {
                v += bias[c] + resid[(size_t)r*N + c];
                if (pm[r]) v = 0.0f;
            }
            C[(size_t)r*N + c] = v;
        }
    }
}

// ---------------------------------------------------------------------------
// Kernel 3: causal silu-attention with relative bias.
// grid = (N/64, B*H), block=256, dynamic smem.
// NOTE: ts is int32 (JAX x64 is disabled; astype(int64) silently yields i32).
// ---------------------------------------------------------------------------
#define PADW 65
#define SMEM_ATTN ((4*64*PADW)*4 + 64*4*2 + 64*4)

__global__ void attn_kernel(const int* __restrict__ ts,
                            const unsigned char* __restrict__ pm,
                            const float* __restrict__ ts_w,
                            const float* __restrict__ pos_w) {
    extern __shared__ float smem[];
    float* qs = smem;                 // [64][65]
    float* ks = qs + 64*PADW;
    float* vs = ks + 64*PADW;
    float* Ss = vs + 64*PADW;
    int* tsl = (int*)(Ss + 64*PADW);  // [64]
    int* tsj = tsl + 64;              // [64]
    int* pmj = tsj + 64;              // [64]

    int bh = blockIdx.y;
    int b = bh >> 3, h = bh & 7;
    int it = blockIdx.x, i0 = it * 64;
    int tid = threadIdx.x;
    int tx = tid & 15, ty = tid >> 4;

    // load Q tile (offset 1024 in uvqk-out) into qs
    #pragma unroll
    for (int f = 0; f < 4; f++) {
        int id = f*256 + tid, r = id >> 4, c = (id & 15) << 2;
        float4 v = *(const float4*)&g_uo[((size_t)(b*NSEQ + i0 + r))*EOUT + 1024 + h*64 + c];
        qs[r*PADW + c + 0] = v.x; qs[r*PADW + c + 1] = v.y;
        qs[r*PADW + c + 2] = v.z; qs[r*PADW + c + 3] = v.w;
    }
    if (tid < 64) {
        int ip = i0 + tid + 1; if (ip > NSEQ - 1) ip = NSEQ - 1;
        tsl[tid] = ts[b*NSEQ + ip];
    }

    float o[4][4];
    #pragma unroll
    for (int i = 0; i < 4; i++)
        #pragma unroll
        for (int d = 0; d < 4; d++) o[i][d] = 0.0f;

    for (int jt = 0; jt <= it; jt++) {
        int j0 = jt * 64;
        __syncthreads();   // protect ks/vs/tsj from previous iteration's phase B
        // load K (off 1536) and V (off 512) tiles
        #pragma unroll
        for (int f = 0; f < 4; f++) {
            int id = f*256 + tid, r = id >> 4, c = (id & 15) << 2;
            size_t base = ((size_t)(b*NSEQ + j0 + r))*EOUT + h*64 + c;
            float4 kv = *(const float4*)&g_uo[base + 1536];
            ks[r*PADW + c + 0] = kv.x; ks[r*PADW + c + 1] = kv.y;
            ks[r*PADW + c + 2] = kv.z; ks[r*PADW + c + 3] = kv.w;
            float4 vv = *(const float4*)&g_uo[base + 512];
            vs[r*PADW + c + 0] = vv.x; vs[r*PADW + c + 1] = vv.y;
            vs[r*PADW + c + 2] = vv.z; vs[r*PADW + c + 3] = vv.w;
        }
        if (tid < 64) {
            tsj[tid] = ts[b*NSEQ + j0 + tid];
            pmj[tid] = pm[b*NSEQ + j0 + tid];
        }
        __syncthreads();

        // phase A: S = Q K^T  (each thread: 4x4)
        float sa[4][4];
        #pragma unroll
        for (int i = 0; i < 4; i++)
            #pragma unroll
            for (int j = 0; j < 4; j++) sa[i][j] = 0.0f;
        for (int kk = 0; kk < 64; kk++) {
            float a0 = qs[(ty*4 + 0)*PADW + kk];
            float a1 = qs[(ty*4 + 1)*PADW + kk];
            float a2 = qs[(ty*4 + 2)*PADW + kk];
            float a3 = qs[(ty*4 + 3)*PADW + kk];
            float b0 = ks[(tx*4 + 0)*PADW + kk];
            float b1 = ks[(tx*4 + 1)*PADW + kk];
            float b2 = ks[(tx*4 + 2)*PADW + kk];
            float b3 = ks[(tx*4 + 3)*PADW + kk];
            sa[0][0]+=a0*b0; sa[0][1]+=a0*b1; sa[0][2]+=a0*b2; sa[0][3]+=a0*b3;
            sa[1][0]+=a1*b0; sa[1][1]+=a1*b1; sa[1][2]+=a1*b2; sa[1][3]+=a1*b3;
            sa[2][0]+=a2*b0; sa[2][1]+=a2*b1; sa[2][2]+=a2*b2; sa[2][3]+=a2*b3;
            sa[3][0]+=a3*b0; sa[3][1]+=a3*b1; sa[3][2]+=a3*b2; sa[3][3]+=a3*b3;
        }
        // bias + silu + mask -> Ss
        #pragma unroll
        for (int i = 0; i < 4; i++) {
            int ig = i0 + ty*4 + i;
            int tl = tsl[ty*4 + i];
            #pragma unroll
            for (int j = 0; j < 4; j++) {
                int jg = j0 + tx*4 + j;
                float s = sa[i][j] + pos_w[jg - ig + NSEQ - 1];
                int d = tl - tsj[tx*4 + j];
                if (d < 0) d = -d;
                if (d < 1) d = 1;
                int bk = (int)(logf((float)d) / 0.301f);
                bk = min(max(bk, 0), 64);
                s += ts_w[bk];
                s = s / (1.0f + expf(-s)) * (1.0f / NSEQ);
                if (jg > ig || pmj[tx*4 + j]) s = 0.0f;
                Ss[(ty*4 + i)*PADW + tx*4 + j] = s;
            }
        }
        __syncthreads();

        // phase B: O += S @ V  (each thread: rows ty*4.., dcols tx*4..)
        for (int jj = 0; jj < 64; jj++) {
            float s0 = Ss[(ty*4 + 0)*PADW + jj];
            float s1 = Ss[(ty*4 + 1)*PADW + jj];
            float s2 = Ss[(ty*4 + 2)*PADW + jj];
            float s3 = Ss[(ty*4 + 3)*PADW + jj];
            float v0 = vs[jj*PADW + tx*4 + 0];
            float v1 = vs[jj*PADW + tx*4 + 1];
            float v2 = vs[jj*PADW + tx*4 + 2];
            float v3 = vs[jj*PADW + tx*4 + 3];
            o[0][0]+=s0*v0; o[0][1]+=s0*v1; o[0][2]+=s0*v2; o[0][3]+=s0*v3;
            o[1][0]+=s1*v0; o[1][1]+=s1*v1; o[1][2]+=s1*v2; o[1][3]+=s1*v3;
            o[2][0]+=s2*v0; o[2][1]+=s2*v1; o[2][2]+=s2*v2; o[2][3]+=s2*v3;
            o[3][0]+=s3*v0; o[3][1]+=s3*v1; o[3][2]+=s3*v2; o[3][3]+=s3*v3;
        }
    }

    // write ao[b, i, h*64 + d]
    #pragma unroll
    for (int i = 0; i < 4; i++)
        #pragma unroll
        for (int d = 0; d < 4; d++)
            g_ao[((size_t)(b*NSEQ + i0 + ty*4 + i))*DMODEL + h*64 + tx*4 + d] = o[i][d];
}

// ---------------------------------------------------------------------------
// Launch
// ---------------------------------------------------------------------------
extern "C" void kernel_launch(void* const* d_in, const int* in_sizes, int n_in,
                              void* d_out, int out_size) {
    const float*          x      = (const float*)d_in[0];
    const int*            ts     = (const int*)d_in[1];     // int32! (JAX x64 off)
    /* d_in[2] = cm (causal mask) — analytic triu(k=1), unused */
    const unsigned char*  pm     = (const unsigned char*)d_in[3];
    const float*          uvqk   = (const float*)d_in[4];
    const float*          o_w    = (const float*)d_in[5];
    const float*          o_b    = (const float*)d_in[6];
    const float*          ln_x_w = (const float*)d_in[7];
    const float*          ln_x_b = (const float*)d_in[8];
    const float*          ln_a_w = (const float*)d_in[9];
    const float*          ln_a_b = (const float*)d_in[10];
    const float*          ts_w   = (const float*)d_in[11];
    const float*          pos_w  = (const float*)d_in[12];
    float*                out    = (float*)d_out;

    float *p_nx, *p_uo, *p_t;
    cudaGetSymbolAddress((void**)&p_nx, g_nx);
    cudaGetSymbolAddress((void**)&p_uo, g_uo);
    cudaGetSymbolAddress((void**)&p_t,  g_t);

    cudaFuncSetAttribute(attn_kernel,
                         cudaFuncAttributeMaxDynamicSharedMemorySize, SMEM_ATTN);

    // 1. LN(x)
    ln_x_kernel<<<ROWS, 256>>>(x, ln_x_w, ln_x_b);

    // 2. uvqk GEMM + silu: [4096,512] @ [512,2048]
    gemm_kernel<0><<<dim3(EOUT/64, ROWS/128), 256>>>(
        p_nx, uvqk, p_uo, ROWS, EOUT, DMODEL, nullptr, nullptr, nullptr);

    // 3. causal silu-attention with relative bias
    attn_kernel<<<dim3(NSEQ/64, NB*NH), 256, SMEM_ATTN>>>(ts, pm, ts_w, pos_w);

    // 4. t = u * LN(ao)
    ln_a_kernel<<<ROWS, 256>>>(ln_a_w, ln_a_b);

    // 5. y = t @ o_w + o_b + x, masked by pm: [4096,512] @ [512,512]
    gemm_kernel<1><<<dim3(DMODEL/64, ROWS/128), 256>>>(
        p_t, o_w, out, ROWS, DMODEL, DMODEL, o_b, x, pm);
}

// round 6
// speedup vs baseline: 1.1648x; 1.1648x over previous
#include <cuda_runtime.h>
#include <cuda_bf16.h>
#include <cstdint>
#include <math.h>

// Problem constants
#define NB     4
#define NSEQ   1024
#define DMODEL 512
#define NH     8
#define HD     64
#define EOUT   2048          // 2*H*Dv + 2*H*Dq
#define ROWS   (NB*NSEQ)     // 4096

// ---------------------------------------------------------------------------
// Scratch (allocation-free -> __device__ globals)
// ---------------------------------------------------------------------------
__device__ float g_uo[ROWS*EOUT];     // silu(nx @ uvqk): [u|v|q|k]  (fp32, attn input)
__device__ float g_ao[ROWS*DMODEL];   // attention output
__device__ __nv_bfloat16 g_nxh[ROWS*DMODEL], g_nxl[ROWS*DMODEL];  // LN(x) hi/lo
__device__ __nv_bfloat16 g_th [ROWS*DMODEL], g_tl [ROWS*DMODEL];  // u*LN(ao) hi/lo
__device__ __nv_bfloat16 g_B1h[EOUT*DMODEL], g_B1l[EOUT*DMODEL];  // uvqk^T  [2048][512]
__device__ __nv_bfloat16 g_B2h[DMODEL*DMODEL], g_B2l[DMODEL*DMODEL]; // o_w^T [512][512]

// ---------------------------------------------------------------------------
// mma.sync helpers (sm_80-era PTX, legal on compute_103)
// ---------------------------------------------------------------------------
__device__ __forceinline__ uint32_t smem_to_u32(const void* p) {
    uint32_t a;
    asm("{ .reg .u64 t; cvta.to.shared.u64 t, %1; cvt.u32.u64 %0, t; }" : "=r"(a) : "l"(p));
    return a;
}
__device__ __forceinline__ void ldsm4(uint32_t* r, uint32_t addr) {
    asm volatile("ldmatrix.sync.aligned.m8n8.x4.shared.b16 {%0,%1,%2,%3}, [%4];"
        : "=r"(r[0]), "=r"(r[1]), "=r"(r[2]), "=r"(r[3]) : "r"(addr));
}
__device__ __forceinline__ void mma16816(float* c, const uint32_t* a, const uint32_t* b) {
    asm volatile("mma.sync.aligned.m16n8k16.row.col.f32.bf16.bf16.f32 "
        "{%0,%1,%2,%3}, {%4,%5,%6,%7}, {%8,%9}, {%0,%1,%2,%3};"
        : "+f"(c[0]), "+f"(c[1]), "+f"(c[2]), "+f"(c[3])
        : "r"(a[0]), "r"(a[1]), "r"(a[2]), "r"(a[3]), "r"(b[0]), "r"(b[1]));
}

// ---------------------------------------------------------------------------
// Block reduction (256 threads)
// ---------------------------------------------------------------------------
__device__ __forceinline__ float blk_reduce_sum(float v, float* sm) {
    int tid = threadIdx.x;
    #pragma unroll
    for (int o = 16; o > 0; o >>= 1) v += __shfl_down_sync(0xffffffffu, v, o);
    if ((tid & 31) == 0) sm[tid >> 5] = v;
    __syncthreads();
    if (tid < 32) {
        float t = (tid < 8) ? sm[tid] : 0.0f;
        #pragma unroll
        for (int o = 4; o > 0; o >>= 1) t += __shfl_down_sync(0xffffffffu, t, o);
        if (tid == 0) sm[0] = t;
    }
    __syncthreads();
    float r = sm[0];
    __syncthreads();
    return r;
}

__device__ __forceinline__ void split_write(__nv_bfloat16* ph, __nv_bfloat16* pl,
                                            size_t idx, float v) {
    __nv_bfloat16 h = __float2bfloat16(v);
    ph[idx] = h;
    pl[idx] = __float2bfloat16(v - __bfloat162float(h));
}

// ---------------------------------------------------------------------------
// Kernel 1: LayerNorm(x) -> g_nxh/g_nxl (bf16 split)    grid=4096, block=256
// ---------------------------------------------------------------------------
__global__ void ln_x_kernel(const float* __restrict__ x,
                            const float* __restrict__ w,
                            const float* __restrict__ b) {
    __shared__ float sm[8];
    int r = blockIdx.x, tid = threadIdx.x;
    const float* xr = x + (size_t)r * DMODEL;
    float v0 = xr[tid], v1 = xr[tid + 256];
    float mean = blk_reduce_sum(v0 + v1, sm) * (1.0f / DMODEL);
    float d0 = v0 - mean, d1 = v1 - mean;
    float var = blk_reduce_sum(d0*d0 + d1*d1, sm) * (1.0f / DMODEL);
    float inv = rsqrtf(var + 1e-5f);
    split_write(g_nxh, g_nxl, (size_t)r*DMODEL + tid,       d0*inv*w[tid]       + b[tid]);
    split_write(g_nxh, g_nxl, (size_t)r*DMODEL + tid + 256, d1*inv*w[tid + 256] + b[tid + 256]);
}

// ---------------------------------------------------------------------------
// Kernel 4: t = u * LayerNorm(ao) -> g_th/g_tl          grid=4096, block=256
// ---------------------------------------------------------------------------
__global__ void ln_a_kernel(const float* __restrict__ w,
                            const float* __restrict__ b) {
    __shared__ float sm[8];
    int r = blockIdx.x, tid = threadIdx.x;
    const float* ar = g_ao + (size_t)r * DMODEL;
    float v0 = ar[tid], v1 = ar[tid + 256];
    float mean = blk_reduce_sum(v0 + v1, sm) * (1.0f / DMODEL);
    float d0 = v0 - mean, d1 = v1 - mean;
    float var = blk_reduce_sum(d0*d0 + d1*d1, sm) * (1.0f / DMODEL);
    float inv = rsqrtf(var + 1e-5f);
    const float* ur = g_uo + (size_t)r * EOUT;   // u = first 512 cols
    split_write(g_th, g_tl, (size_t)r*DMODEL + tid,
                (d0*inv*w[tid] + b[tid]) * ur[tid]);
    split_write(g_th, g_tl, (size_t)r*DMODEL + tid + 256,
                (d1*inv*w[tid + 256] + b[tid + 256]) * ur[tid + 256]);
}

// ---------------------------------------------------------------------------
// Transpose + bf16 split: in[K][N] fp32 -> oh/ol[N][K] bf16
// grid (N/32, K/32), block (32, 8)
// ---------------------------------------------------------------------------
__global__ void tsplit_kernel(const float* __restrict__ in,
                              __nv_bfloat16* __restrict__ oh,
                              __nv_bfloat16* __restrict__ ol,
                              int K, int N) {
    __shared__ float tile[32][33];
    int n0 = blockIdx.x * 32, k0 = blockIdx.y * 32;
    int tx = threadIdx.x, ty = threadIdx.y;
    #pragma unroll
    for (int i = 0; i < 4; i++)
        tile[ty + i*8][tx] = in[(size_t)(k0 + ty + i*8) * N + n0 + tx];
    __syncthreads();
    #pragma unroll
    for (int i = 0; i < 4; i++) {
        float v = tile[tx][ty + i*8];
        __nv_bfloat16 h = __float2bfloat16(v);
        size_t o = (size_t)(n0 + ty + i*8) * K + k0 + tx;
        oh[o] = h;
        ol[o] = __float2bfloat16(v - __bfloat162float(h));
    }
}

// ---------------------------------------------------------------------------
// mma.sync bf16-split GEMM: C[M,N] = sum_seg Aseg @ Bseg^T
//   A segs: [M,512] bf16 K-major. B segs: [N,512] bf16 K-major (pre-transposed).
//   CTA tile 128x128, 8 warps in 2(m)x4(n), warp tile 64x32.
//   K loop: 24 chunks of 64 (3 segments x 8), single-buffered padded smem.
// EPI 0: silu.  EPI 1: +bias[c]+resid[r,c], zero if pm[r].
// ---------------------------------------------------------------------------
#define KSEG   512
#define NCHUNK 24
#define SPAD   72    // 64 + 8 bf16 pad -> 144B row stride, ldmatrix conflict-free

template<int EPI>
__global__ void __launch_bounds__(256)
mma_gemm(const __nv_bfloat16* __restrict__ A0, const __nv_bfloat16* __restrict__ A1,
         const __nv_bfloat16* __restrict__ A2,
         const __nv_bfloat16* __restrict__ B0, const __nv_bfloat16* __restrict__ B1,
         const __nv_bfloat16* __restrict__ B2,
         float* __restrict__ C, int N,
         const float* __restrict__ bias, const float* __restrict__ resid,
         const unsigned char* __restrict__ pm) {
    __shared__ __nv_bfloat16 As[128][SPAD];
    __shared__ __nv_bfloat16 Bs[128][SPAD];

    const int tid = threadIdx.x, wid = tid >> 5, lane = tid & 31;
    const int bm = blockIdx.y * 128, bn = blockIdx.x * 128;
    const int wm = wid & 1, wn = wid >> 1;        // warp tile origin: (wm*64, wn*32)

    float acc[4][4][4];                            // [m-frag][n-frag][c0..c3]
    #pragma unroll
    for (int i = 0; i < 4; i++)
        #pragma unroll
        for (int j = 0; j < 4; j++)
            #pragma unroll
            for (int k = 0; k < 4; k++) acc[i][j][k] = 0.0f;

    const __nv_bfloat16* Aseg[3] = {A0, A1, A2};
    const __nv_bfloat16* Bseg[3] = {B0, B1, B2};

    const uint32_t sa = smem_to_u32(As);
    const uint32_t sb = smem_to_u32(Bs);
    // ldmatrix.x4 source address per lane: rows (lane&15), col half (lane>>4)*8
    const int lrow = lane & 15, lcol = (lane >> 4) * 8;

    for (int c = 0; c < NCHUNK; c++) {
        const __nv_bfloat16* Ab = Aseg[c >> 3];
        const __nv_bfloat16* Bb = Bseg[c >> 3];
        const int kc = (c & 7) * 64;
        __syncthreads();
        #pragma unroll
        for (int i = 0; i < 4; i++) {
            int id = i*256 + tid, row = id >> 3, col = (id & 7) * 8;
            *(uint4*)&As[row][col] = *(const uint4*)(Ab + (size_t)(bm + row)*KSEG + kc + col);
            *(uint4*)&Bs[row][col] = *(const uint4*)(Bb + (size_t)(bn + row)*KSEG + kc + col);
        }
        __syncthreads();

        #pragma unroll
        for (int ks = 0; ks < 4; ks++) {           // 4 x k16 per chunk
            uint32_t af[4][4], bf[2][4];
            #pragma unroll
            for (int fm = 0; fm < 4; fm++) {
                int row = wm*64 + fm*16 + lrow;
                ldsm4(af[fm], sa + (row*SPAD + ks*16 + lcol) * 2);
            }
            #pragma unroll
            for (int g = 0; g < 2; g++) {
                int row = wn*32 + g*16 + lrow;
                ldsm4(bf[g], sb + (row*SPAD + ks*16 + lcol) * 2);
            }
            #pragma unroll
            for (int fm = 0; fm < 4; fm++) {
                #pragma unroll
                for (int fn = 0; fn < 4; fn++) {
                    uint32_t bb[2] = { bf[fn >> 1][(fn & 1) + 0],
                                       bf[fn >> 1][(fn & 1) + 2] };
                    mma16816(acc[fm][fn], af[fm], bb);
                }
            }
        }
    }

    // Epilogue: c0,c1 -> row m+(lane>>2), cols n+2*(lane&3); c2,c3 -> row +8
    #pragma unroll
    for (int fm = 0; fm < 4; fm++) {
        #pragma unroll
        for (int half = 0; half < 2; half++) {
            int r = bm + wm*64 + fm*16 + (lane >> 2) + half*8;
            #pragma unroll
            for (int fn = 0; fn < 4; fn++) {
                int cc = bn + wn*32 + fn*8 + (lane & 3)*2;
                float2 v;
                v.x = acc[fm][fn][half*2 + 0];
                v.y = acc[fm][fn][half*2 + 1];
                if (EPI == 0) {
                    v.x = v.x / (1.0f + expf(-v.x));
                    v.y = v.y / (1.0f + expf(-v.y));
                } else {
                    v.x += bias[cc]     + resid[(size_t)r*N + cc];
                    v.y += bias[cc + 1] + resid[(size_t)r*N + cc + 1];
                    if (pm[r]) { v.x = 0.0f; v.y = 0.0f; }
                }
                *(float2*)&C[(size_t)r*N + cc] = v;
            }
        }
    }
}

// ---------------------------------------------------------------------------
// Kernel 3: causal silu-attention with relative bias (SIMT, fp32).
// grid = (N/64, B*H), block=256, dynamic smem.  ts is int32.
// ---------------------------------------------------------------------------
#define PADW 65
#define SMEM_ATTN ((4*64*PADW)*4 + 64*4*2 + 64*4)

__global__ void attn_kernel(const int* __restrict__ ts,
                            const unsigned char* __restrict__ pm,
                            const float* __restrict__ ts_w,
                            const float* __restrict__ pos_w) {
    extern __shared__ float smem[];
    float* qs = smem;                 // [64][65]
    float* ks = qs + 64*PADW;
    float* vs = ks + 64*PADW;
    float* Ss = vs + 64*PADW;
    int* tsl = (int*)(Ss + 64*PADW);  // [64]
    int* tsj = tsl + 64;              // [64]
    int* pmj = tsj + 64;              // [64]

    int bh = blockIdx.y;
    int b = bh >> 3, h = bh & 7;
    int it = blockIdx.x, i0 = it * 64;
    int tid = threadIdx.x;
    int tx = tid & 15, ty = tid >> 4;

    #pragma unroll
    for (int f = 0; f < 4; f++) {
        int id = f*256 + tid, r = id >> 4, c = (id & 15) << 2;
        float4 v = *(const float4*)&g_uo[((size_t)(b*NSEQ + i0 + r))*EOUT + 1024 + h*64 + c];
        qs[r*PADW + c + 0] = v.x; qs[r*PADW + c + 1] = v.y;
        qs[r*PADW + c + 2] = v.z; qs[r*PADW + c + 3] = v.w;
    }
    if (tid < 64) {
        int ip = i0 + tid + 1; if (ip > NSEQ - 1) ip = NSEQ - 1;
        tsl[tid] = ts[b*NSEQ + ip];
    }

    float o[4][4];
    #pragma unroll
    for (int i = 0; i < 4; i++)
        #pragma unroll
        for (int d = 0; d < 4; d++) o[i][d] = 0.0f;

    for (int jt = 0; jt <= it; jt++) {
        int j0 = jt * 64;
        __syncthreads();
        #pragma unroll
        for (int f = 0; f < 4; f++) {
            int id = f*256 + tid, r = id >> 4, c = (id & 15) << 2;
            size_t base = ((size_t)(b*NSEQ + j0 + r))*EOUT + h*64 + c;
            float4 kv = *(const float4*)&g_uo[base + 1536];
            ks[r*PADW + c + 0] = kv.x; ks[r*PADW + c + 1] = kv.y;
            ks[r*PADW + c + 2] = kv.z; ks[r*PADW + c + 3] = kv.w;
            float4 vv = *(const float4*)&g_uo[base + 512];
            vs[r*PADW + c + 0] = vv.x; vs[r*PADW + c + 1] = vv.y;
            vs[r*PADW + c + 2] = vv.z; vs[r*PADW + c + 3] = vv.w;
        }
        if (tid < 64) {
            tsj[tid] = ts[b*NSEQ + j0 + tid];
            pmj[tid] = pm[b*NSEQ + j0 + tid];
        }
        __syncthreads();

        float sa[4][4];
        #pragma unroll
        for (int i = 0; i < 4; i++)
            #pragma unroll
            for (int j = 0; j < 4; j++) sa[i][j] = 0.0f;
        for (int kk = 0; kk < 64; kk++) {
            float a0 = qs[(ty*4 + 0)*PADW + kk];
            float a1 = qs[(ty*4 + 1)*PADW + kk];
            float a2 = qs[(ty*4 + 2)*PADW + kk];
            float a3 = qs[(ty*4 + 3)*PADW + kk];
            float b0 = ks[(tx*4 + 0)*PADW + kk];
            float b1 = ks[(tx*4 + 1)*PADW + kk];
            float b2 = ks[(tx*4 + 2)*PADW + kk];
            float b3 = ks[(tx*4 + 3)*PADW + kk];
            sa[0][0]+=a0*b0; sa[0][1]+=a0*b1; sa[0][2]+=a0*b2; sa[0][3]+=a0*b3;
            sa[1][0]+=a1*b0; sa[1][1]+=a1*b1; sa[1][2]+=a1*b2; sa[1][3]+=a1*b3;
            sa[2][0]+=a2*b0; sa[2][1]+=a2*b1; sa[2][2]+=a2*b2; sa[2][3]+=a2*b3;
            sa[3][0]+=a3*b0; sa[3][1]+=a3*b1; sa[3][2]+=a3*b2; sa[3][3]+=a3*b3;
        }
        #pragma unroll
        for (int i = 0; i < 4; i++) {
            int ig = i0 + ty*4 + i;
            int tl = tsl[ty*4 + i];
            #pragma unroll
            for (int j = 0; j < 4; j++) {
                int jg = j0 + tx*4 + j;
                float s = sa[i][j] + pos_w[jg - ig + NSEQ - 1];
                int d = tl - tsj[tx*4 + j];
                if (d < 0) d = -d;
                if (d < 1) d = 1;
                int bk = (int)(logf((float)d) / 0.301f);
                bk = min(max(bk, 0), 64);
                s += ts_w[bk];
                s = s / (1.0f + expf(-s)) * (1.0f / NSEQ);
                if (jg > ig || pmj[tx*4 + j]) s = 0.0f;
                Ss[(ty*4 + i)*PADW + tx*4 + j] = s;
            }
        }
        __syncthreads();

        for (int jj = 0; jj < 64; jj++) {
            float s0 = Ss[(ty*4 + 0)*PADW + jj];
            float s1 = Ss[(ty*4 + 1)*PADW + jj];
            float s2 = Ss[(ty*4 + 2)*PADW + jj];
            float s3 = Ss[(ty*4 + 3)*PADW + jj];
            float v0 = vs[jj*PADW + tx*4 + 0];
            float v1 = vs[jj*PADW + tx*4 + 1];
            float v2 = vs[jj*PADW + tx*4 + 2];
            float v3 = vs[jj*PADW + tx*4 + 3];
            o[0][0]+=s0*v0; o[0][1]+=s0*v1; o[0][2]+=s0*v2; o[0][3]+=s0*v3;
            o[1][0]+=s1*v0; o[1][1]+=s1*v1; o[1][2]+=s1*v2; o[1][3]+=s1*v3;
            o[2][0]+=s2*v0; o[2][1]+=s2*v1; o[2][2]+=s2*v2; o[2][3]+=s2*v3;
            o[3][0]+=s3*v0; o[3][1]+=s3*v1; o[3][2]+=s3*v2; o[3][3]+=s3*v3;
        }
    }

    #pragma unroll
    for (int i = 0; i < 4; i++)
        #pragma unroll
        for (int d = 0; d < 4; d++)
            g_ao[((size_t)(b*NSEQ + i0 + ty*4 + i))*DMODEL + h*64 + tx*4 + d] = o[i][d];
}

// ---------------------------------------------------------------------------
// Launch
// ---------------------------------------------------------------------------
extern "C" void kernel_launch(void* const* d_in, const int* in_sizes, int n_in,
                              void* d_out, int out_size) {
    const float*          x      = (const float*)d_in[0];
    const int*            ts     = (const int*)d_in[1];     // int32 (JAX x64 off)
    /* d_in[2] = cm — analytic triu(k=1), unused */
    const unsigned char*  pm     = (const unsigned char*)d_in[3];
    const float*          uvqk   = (const float*)d_in[4];
    const float*          o_w    = (const float*)d_in[5];
    const float*          o_b    = (const float*)d_in[6];
    const float*          ln_x_w = (const float*)d_in[7];
    const float*          ln_x_b = (const float*)d_in[8];
    const float*          ln_a_w = (const float*)d_in[9];
    const float*          ln_a_b = (const float*)d_in[10];
    const float*          ts_w   = (const float*)d_in[11];
    const float*          pos_w  = (const float*)d_in[12];
    float*                out    = (float*)d_out;

    float *p_uo;
    __nv_bfloat16 *p_nxh, *p_nxl, *p_th, *p_tl, *p_B1h, *p_B1l, *p_B2h, *p_B2l;
    cudaGetSymbolAddress((void**)&p_uo,  g_uo);
    cudaGetSymbolAddress((void**)&p_nxh, g_nxh);
    cudaGetSymbolAddress((void**)&p_nxl, g_nxl);
    cudaGetSymbolAddress((void**)&p_th,  g_th);
    cudaGetSymbolAddress((void**)&p_tl,  g_tl);
    cudaGetSymbolAddress((void**)&p_B1h, g_B1h);
    cudaGetSymbolAddress((void**)&p_B1l, g_B1l);
    cudaGetSymbolAddress((void**)&p_B2h, g_B2h);
    cudaGetSymbolAddress((void**)&p_B2l, g_B2l);

    cudaFuncSetAttribute(attn_kernel,
                         cudaFuncAttributeMaxDynamicSharedMemorySize, SMEM_ATTN);

    // 0. transpose + split weights (uvqk -> [2048][512], o_w -> [512][512])
    tsplit_kernel<<<dim3(EOUT/32, DMODEL/32), dim3(32, 8)>>>(uvqk, p_B1h, p_B1l, DMODEL, EOUT);
    tsplit_kernel<<<dim3(DMODEL/32, DMODEL/32), dim3(32, 8)>>>(o_w, p_B2h, p_B2l, DMODEL, DMODEL);

    // 1. LN(x) -> bf16 hi/lo
    ln_x_kernel<<<ROWS, 256>>>(x, ln_x_w, ln_x_b);

    // 2. uvqk GEMM + silu on HMMA:  [4096,512] @ [512,2048]
    //    C = nx_h@B_h + nx_l@B_h + nx_h@B_l
    mma_gemm<0><<<dim3(EOUT/128, ROWS/128), 256>>>(
        p_nxh, p_nxl, p_nxh, p_B1h, p_B1h, p_B1l,
        p_uo, EOUT, nullptr, nullptr, nullptr);

    // 3. causal silu-attention with relative bias
    attn_kernel<<<dim3(NSEQ/64, NB*NH), 256, SMEM_ATTN>>>(ts, pm, ts_w, pos_w);

    // 4. t = u * LN(ao) -> bf16 hi/lo
    ln_a_kernel<<<ROWS, 256>>>(ln_a_w, ln_a_b);

    // 5. y = t @ o_w + o_b + x (pm-masked) on HMMA: [4096,512] @ [512,512]
    mma_gemm<1><<<dim3(DMODEL/128, ROWS/128), 256>>>(
        p_th, p_tl, p_th, p_B2h, p_B2h, p_B2l,
        out, DMODEL, o_b, x, pm);
}

// round 8
// speedup vs baseline: 1.8916x; 1.6241x over previous
#include <cuda_runtime.h>
#include <cuda_bf16.h>
#include <cstdint>
#include <math.h>

// Problem constants
#define NB     4
#define NSEQ   1024
#define DMODEL 512
#define NH     8
#define HD     64
#define EOUT   2048          // 2*H*Dv + 2*H*Dq
#define ROWS   (NB*NSEQ)     // 4096

// Single dynamic-smem symbol (typed via casts in each kernel)
extern __shared__ __align__(128) unsigned char dynsmem[];

// ---------------------------------------------------------------------------
// Scratch (allocation-free -> __device__ globals)
// ---------------------------------------------------------------------------
__device__ float g_ao[ROWS*DMODEL];   // attention output
__device__ __nv_bfloat16 g_uoh[ROWS*EOUT], g_uol[ROWS*EOUT];      // silu(nx@uvqk) hi/lo
__device__ __nv_bfloat16 g_nxh[ROWS*DMODEL], g_nxl[ROWS*DMODEL];  // LN(x) hi/lo
__device__ __nv_bfloat16 g_th [ROWS*DMODEL], g_tl [ROWS*DMODEL];  // u*LN(ao) hi/lo
__device__ __nv_bfloat16 g_B1h[EOUT*DMODEL], g_B1l[EOUT*DMODEL];  // uvqk^T  [2048][512]
__device__ __nv_bfloat16 g_B2h[DMODEL*DMODEL], g_B2l[DMODEL*DMODEL]; // o_w^T [512][512]

// ---------------------------------------------------------------------------
// mma.sync helpers (sm_80-era PTX, legal on compute_103)
// ---------------------------------------------------------------------------
__device__ __forceinline__ uint32_t smem_to_u32(const void* p) {
    uint32_t a;
    asm("{ .reg .u64 t; cvta.to.shared.u64 t, %1; cvt.u32.u64 %0, t; }" : "=r"(a) : "l"(p));
    return a;
}
__device__ __forceinline__ void ldsm4(uint32_t* r, uint32_t addr) {
    asm volatile("ldmatrix.sync.aligned.m8n8.x4.shared.b16 {%0,%1,%2,%3}, [%4];"
        : "=r"(r[0]), "=r"(r[1]), "=r"(r[2]), "=r"(r[3]) : "r"(addr));
}
__device__ __forceinline__ void ldsm4t(uint32_t* r, uint32_t addr) {
    asm volatile("ldmatrix.sync.aligned.m8n8.x4.trans.shared.b16 {%0,%1,%2,%3}, [%4];"
        : "=r"(r[0]), "=r"(r[1]), "=r"(r[2]), "=r"(r[3]) : "r"(addr));
}
__device__ __forceinline__ void mma16816(float* c, const uint32_t* a, const uint32_t* b) {
    asm volatile("mma.sync.aligned.m16n8k16.row.col.f32.bf16.bf16.f32 "
        "{%0,%1,%2,%3}, {%4,%5,%6,%7}, {%8,%9}, {%0,%1,%2,%3};"
        : "+f"(c[0]), "+f"(c[1]), "+f"(c[2]), "+f"(c[3])
        : "r"(a[0]), "r"(a[1]), "r"(a[2]), "r"(a[3]), "r"(b[0]), "r"(b[1]));
}
__device__ __forceinline__ void cp16(uint32_t s, const void* g) {
    asm volatile("cp.async.cg.shared.global [%0], [%1], 16;" :: "r"(s), "l"(g));
}
#define CP_COMMIT() asm volatile("cp.async.commit_group;")
#define CP_WAIT(N)  asm volatile("cp.async.wait_group %0;" :: "n"(N))

__device__ __forceinline__ uint32_t pack_hi(float a, float b) {
    __nv_bfloat162 t = __floats2bfloat162_rn(a, b);
    return *(uint32_t*)&t;
}
__device__ __forceinline__ uint32_t pack_lo(float a, float b, uint32_t hi) {
    __nv_bfloat162 h = *(__nv_bfloat162*)&hi;
    __nv_bfloat162 t = __floats2bfloat162_rn(a - __bfloat162float(h.x),
                                             b - __bfloat162float(h.y));
    return *(uint32_t*)&t;
}

// ---------------------------------------------------------------------------
// Block reduction (256 threads)
// ---------------------------------------------------------------------------
__device__ __forceinline__ float blk_reduce_sum(float v, float* sm) {
    int tid = threadIdx.x;
    #pragma unroll
    for (int o = 16; o > 0; o >>= 1) v += __shfl_down_sync(0xffffffffu, v, o);
    if ((tid & 31) == 0) sm[tid >> 5] = v;
    __syncthreads();
    if (tid < 32) {
        float t = (tid < 8) ? sm[tid] : 0.0f;
        #pragma unroll
        for (int o = 4; o > 0; o >>= 1) t += __shfl_down_sync(0xffffffffu, t, o);
        if (tid == 0) sm[0] = t;
    }
    __syncthreads();
    float r = sm[0];
    __syncthreads();
    return r;
}

__device__ __forceinline__ void split_write(__nv_bfloat16* ph, __nv_bfloat16* pl,
                                            size_t idx, float v) {
    __nv_bfloat16 h = __float2bfloat16(v);
    ph[idx] = h;
    pl[idx] = __float2bfloat16(v - __bfloat162float(h));
}

// ---------------------------------------------------------------------------
// Kernel 1: LayerNorm(x) -> g_nxh/g_nxl          grid=4096, block=256
// ---------------------------------------------------------------------------
__global__ void ln_x_kernel(const float* __restrict__ x,
                            const float* __restrict__ w,
                            const float* __restrict__ b) {
    __shared__ float sm[8];
    int r = blockIdx.x, tid = threadIdx.x;
    const float* xr = x + (size_t)r * DMODEL;
    float v0 = xr[tid], v1 = xr[tid + 256];
    float mean = blk_reduce_sum(v0 + v1, sm) * (1.0f / DMODEL);
    float d0 = v0 - mean, d1 = v1 - mean;
    float var = blk_reduce_sum(d0*d0 + d1*d1, sm) * (1.0f / DMODEL);
    float inv = rsqrtf(var + 1e-5f);
    split_write(g_nxh, g_nxl, (size_t)r*DMODEL + tid,       d0*inv*w[tid]       + b[tid]);
    split_write(g_nxh, g_nxl, (size_t)r*DMODEL + tid + 256, d1*inv*w[tid + 256] + b[tid + 256]);
}

// ---------------------------------------------------------------------------
// Kernel 4: t = u * LayerNorm(ao) -> g_th/g_tl   grid=4096, block=256
// u reconstructed from hi+lo.
// ---------------------------------------------------------------------------
__global__ void ln_a_kernel(const float* __restrict__ w,
                            const float* __restrict__ b) {
    __shared__ float sm[8];
    int r = blockIdx.x, tid = threadIdx.x;
    const float* ar = g_ao + (size_t)r * DMODEL;
    float v0 = ar[tid], v1 = ar[tid + 256];
    float mean = blk_reduce_sum(v0 + v1, sm) * (1.0f / DMODEL);
    float d0 = v0 - mean, d1 = v1 - mean;
    float var = blk_reduce_sum(d0*d0 + d1*d1, sm) * (1.0f / DMODEL);
    float inv = rsqrtf(var + 1e-5f);
    size_t ub = (size_t)r * EOUT;
    float u0 = __bfloat162float(g_uoh[ub + tid])       + __bfloat162float(g_uol[ub + tid]);
    float u1 = __bfloat162float(g_uoh[ub + tid + 256]) + __bfloat162float(g_uol[ub + tid + 256]);
    split_write(g_th, g_tl, (size_t)r*DMODEL + tid,
                (d0*inv*w[tid] + b[tid]) * u0);
    split_write(g_th, g_tl, (size_t)r*DMODEL + tid + 256,
                (d1*inv*w[tid + 256] + b[tid + 256]) * u1);
}

// ---------------------------------------------------------------------------
// Transpose + bf16 split: in[K][N] fp32 -> oh/ol[N][K] bf16
// ---------------------------------------------------------------------------
__global__ void tsplit_kernel(const float* __restrict__ in,
                              __nv_bfloat16* __restrict__ oh,
                              __nv_bfloat16* __restrict__ ol,
                              int K, int N) {
    __shared__ float tile[32][33];
    int n0 = blockIdx.x * 32, k0 = blockIdx.y * 32;
    int tx = threadIdx.x, ty = threadIdx.y;
    #pragma unroll
    for (int i = 0; i < 4; i++)
        tile[ty + i*8][tx] = in[(size_t)(k0 + ty + i*8) * N + n0 + tx];
    __syncthreads();
    #pragma unroll
    for (int i = 0; i < 4; i++) {
        float v = tile[tx][ty + i*8];
        __nv_bfloat16 h = __float2bfloat16(v);
        size_t o = (size_t)(n0 + ty + i*8) * K + k0 + tx;
        oh[o] = h;
        ol[o] = __float2bfloat16(v - __bfloat162float(h));
    }
}

// ---------------------------------------------------------------------------
// cp.async double-buffered bf16-split GEMM (HMMA).
// C[M,N] = sum of Aseg @ Bseg^T over 3 (hi/lo) segment pairs.
// CTA 128x128, 8 warps (2m x 4n), warp 64x32, K chunks of 64.
// EPI 0: silu -> write hi/lo bf16 to Ch/Cl.  EPI 1: fp32 +bias+resid, pm mask.
// ---------------------------------------------------------------------------
#define KSEG   512
#define NCHUNK 24
#define SPAD   72
#define GSTAGE (2*128*SPAD*2)        // bytes per stage (A tile + B tile)
#define SMEM_GEMM (2*GSTAGE)

template<int EPI>
__global__ void __launch_bounds__(256)
mma_gemm(const __nv_bfloat16* __restrict__ A0, const __nv_bfloat16* __restrict__ A1,
         const __nv_bfloat16* __restrict__ A2,
         const __nv_bfloat16* __restrict__ B0, const __nv_bfloat16* __restrict__ B1,
         const __nv_bfloat16* __restrict__ B2,
         float* __restrict__ C,
         __nv_bfloat16* __restrict__ Ch, __nv_bfloat16* __restrict__ Cl, int N,
         const float* __restrict__ bias, const float* __restrict__ resid,
         const unsigned char* __restrict__ pm) {
    const int tid = threadIdx.x, wid = tid >> 5, lane = tid & 31;
    const int bm = blockIdx.y * 128, bn = blockIdx.x * 128;
    const int wm = wid & 1, wn = wid >> 1;

    const __nv_bfloat16* Aseg[3] = {A0, A1, A2};
    const __nv_bfloat16* Bseg[3] = {B0, B1, B2};

    const uint32_t sbase = smem_to_u32(dynsmem);
    const int lrow = lane & 15, lcol = (lane >> 4) * 8;
    // per-thread cp.async coords: 4 rows of A + 4 rows of B per chunk
    const int crow = tid >> 3, ccol = (tid & 7) * 8;   // 32 rows per pass

    float acc[4][4][4];
    #pragma unroll
    for (int i = 0; i < 4; i++)
        #pragma unroll
        for (int j = 0; j < 4; j++)
            #pragma unroll
            for (int k = 0; k < 4; k++) acc[i][j][k] = 0.0f;

    auto issue = [&](int c) {
        const __nv_bfloat16* Ab = Aseg[c >> 3];
        const __nv_bfloat16* Bb = Bseg[c >> 3];
        const int kc = (c & 7) * 64;
        const uint32_t st = sbase + (c & 1) * GSTAGE;
        #pragma unroll
        for (int i = 0; i < 4; i++) {
            int row = crow + i*32;
            cp16(st + (row*SPAD + ccol)*2,
                 Ab + (size_t)(bm + row)*KSEG + kc + ccol);
            cp16(st + (128*SPAD + row*SPAD + ccol)*2,
                 Bb + (size_t)(bn + row)*KSEG + kc + ccol);
        }
        CP_COMMIT();
    };

    issue(0);
    for (int c = 0; c < NCHUNK; c++) {
        if (c + 1 < NCHUNK) { issue(c + 1); CP_WAIT(1); }
        else                { CP_WAIT(0); }
        __syncthreads();
        const uint32_t sa = sbase + (c & 1) * GSTAGE;
        const uint32_t sb = sa + 128*SPAD*2;
        #pragma unroll
        for (int ks = 0; ks < 4; ks++) {
            uint32_t af[4][4], bf[2][4];
            #pragma unroll
            for (int fm = 0; fm < 4; fm++)
                ldsm4(af[fm], sa + ((wm*64 + fm*16 + lrow)*SPAD + ks*16 + lcol)*2);
            #pragma unroll
            for (int g = 0; g < 2; g++)
                ldsm4(bf[g], sb + ((wn*32 + g*16 + lrow)*SPAD + ks*16 + lcol)*2);
            #pragma unroll
            for (int fm = 0; fm < 4; fm++)
                #pragma unroll
                for (int fn = 0; fn < 4; fn++) {
                    uint32_t bb[2] = { bf[fn >> 1][(fn & 1) + 0],
                                       bf[fn >> 1][(fn & 1) + 2] };
                    mma16816(acc[fm][fn], af[fm], bb);
                }
        }
        __syncthreads();
    }

    #pragma unroll
    for (int fm = 0; fm < 4; fm++) {
        #pragma unroll
        for (int half = 0; half < 2; half++) {
            int r = bm + wm*64 + fm*16 + (lane >> 2) + half*8;
            #pragma unroll
            for (int fn = 0; fn < 4; fn++) {
                int cc = bn + wn*32 + fn*8 + (lane & 3)*2;
                float vx = acc[fm][fn][half*2 + 0];
                float vy = acc[fm][fn][half*2 + 1];
                if (EPI == 0) {
                    vx = vx / (1.0f + __expf(-vx));
                    vy = vy / (1.0f + __expf(-vy));
                    uint32_t hi = pack_hi(vx, vy);
                    uint32_t lo = pack_lo(vx, vy, hi);
                    *(uint32_t*)&Ch[(size_t)r*N + cc] = hi;
                    *(uint32_t*)&Cl[(size_t)r*N + cc] = lo;
                } else {
                    vx += bias[cc]     + resid[(size_t)r*N + cc];
                    vy += bias[cc + 1] + resid[(size_t)r*N + cc + 1];
                    if (pm[r]) { vx = 0.0f; vy = 0.0f; }
                    float2 v = {vx, vy};
                    *(float2*)&C[(size_t)r*N + cc] = v;
                }
            }
        }
    }
}

// ---------------------------------------------------------------------------
// Kernel 3: causal silu-attention with relative bias, on HMMA.
// grid (N/64, B*H), block 128 (4 warps, warp = 16 q-rows).
// QK^T: 3-term bf16 split.  S@V: 3-term split, S packed from C-frags.
// ---------------------------------------------------------------------------
#define ATPAD 72
#define ATILE (64*ATPAD*2)           // 9216 B per bf16 tile
#define ATT_QH 0
#define ATT_QL (1*ATILE)
#define ATT_KH (2*ATILE)
#define ATT_KL (3*ATILE)
#define ATT_VH (4*ATILE)
#define ATT_VL (5*ATILE)
#define ATT_INT (6*ATILE)            // tsl[64] tsj[64] pmj[64] i32, tsw[65] f32
#define SMEM_ATTN (ATT_INT + 3*64*4 + 68*4)

__global__ void __launch_bounds__(128)
attn_kernel(const int* __restrict__ ts,
            const unsigned char* __restrict__ pm,
            const float* __restrict__ ts_w,
            const float* __restrict__ pos_w) {
    unsigned char* sm = dynsmem;
    __nv_bfloat16* Qh = (__nv_bfloat16*)(sm + ATT_QH);
    __nv_bfloat16* Ql = (__nv_bfloat16*)(sm + ATT_QL);
    __nv_bfloat16* Kh = (__nv_bfloat16*)(sm + ATT_KH);
    __nv_bfloat16* Kl = (__nv_bfloat16*)(sm + ATT_KL);
    __nv_bfloat16* Vh = (__nv_bfloat16*)(sm + ATT_VH);
    __nv_bfloat16* Vl = (__nv_bfloat16*)(sm + ATT_VL);
    int*   tsl = (int*)(sm + ATT_INT);
    int*   tsj = tsl + 64;
    int*   pmj = tsj + 64;
    float* tsw = (float*)(pmj + 64);

    const int bh = blockIdx.y, b = bh >> 3, h = bh & 7;
    const int it = blockIdx.x, i0 = it * 64;
    const int tid = threadIdx.x, wq = tid >> 5, lane = tid & 31;
    const int lrow = lane & 15, lcol = (lane >> 4) * 8;

    // Q tile (cols 1024 + h*64)
    #pragma unroll
    for (int i = 0; i < 4; i++) {
        int id = i*128 + tid, row = id >> 3, col = (id & 7) * 8;
        size_t src = (size_t)(b*NSEQ + i0 + row)*EOUT + 1024 + h*64 + col;
        *(uint4*)&Qh[row*ATPAD + col] = *(const uint4*)&g_uoh[src];
        *(uint4*)&Ql[row*ATPAD + col] = *(const uint4*)&g_uol[src];
    }
    if (tid < 64) {
        int ip = i0 + tid + 1; if (ip > NSEQ - 1) ip = NSEQ - 1;
        tsl[tid] = ts[b*NSEQ + ip];
    }
    if (tid < 65) tsw[tid] = ts_w[tid];

    float of[8][4];
    #pragma unroll
    for (int f = 0; f < 8; f++)
        #pragma unroll
        for (int r = 0; r < 4; r++) of[f][r] = 0.0f;

    const int row_lo = wq*16 + (lane >> 2);      // C-frag rows
    const int col_in = (lane & 3) * 2;           // C-frag col pair base

    for (int jt = 0; jt <= it; jt++) {
        const int j0 = jt * 64;
        __syncthreads();
        // K (cols 1536+h*64), V (cols 512+h*64) hi/lo tiles
        #pragma unroll
        for (int i = 0; i < 4; i++) {
            int id = i*128 + tid, row = id >> 3, col = (id & 7) * 8;
            size_t basек = (size_t)(b*NSEQ + j0 + row)*EOUT + h*64 + col;
            *(uint4*)&Kh[row*ATPAD + col] = *(const uint4*)&g_uoh[basек + 1536];
            *(uint4*)&Kl[row*ATPAD + col] = *(const uint4*)&g_uol[basек + 1536];
            *(uint4*)&Vh[row*ATPAD + col] = *(const uint4*)&g_uoh[basек + 512];
            *(uint4*)&Vl[row*ATPAD + col] = *(const uint4*)&g_uol[basек + 512];
        }
        if (tid < 64) {
            tsj[tid] = ts[b*NSEQ + j0 + tid];
            pmj[tid] = pm[b*NSEQ + j0 + tid];
        }
        __syncthreads();

        // ---- Phase A: S = Q K^T (3-term split) ----
        float sc[8][4];
        #pragma unroll
        for (int f = 0; f < 8; f++)
            #pragma unroll
            for (int r = 0; r < 4; r++) sc[f][r] = 0.0f;

        const uint32_t sqh = smem_to_u32(Qh), sql = smem_to_u32(Ql);
        const uint32_t skh = smem_to_u32(Kh), skl = smem_to_u32(Kl);
        #pragma unroll
        for (int ks = 0; ks < 4; ks++) {
            uint32_t ah[4], al[4], kh[4][4], kl[4][4];
            ldsm4(ah, sqh + ((wq*16 + lrow)*ATPAD + ks*16 + lcol)*2);
            ldsm4(al, sql + ((wq*16 + lrow)*ATPAD + ks*16 + lcol)*2);
            #pragma unroll
            for (int g = 0; g < 4; g++) {
                ldsm4(kh[g], skh + ((g*16 + lrow)*ATPAD + ks*16 + lcol)*2);
                ldsm4(kl[g], skl + ((g*16 + lrow)*ATPAD + ks*16 + lcol)*2);
            }
            #pragma unroll
            for (int fn = 0; fn < 8; fn++) {
                uint32_t bh_[2] = { kh[fn >> 1][(fn & 1) + 0], kh[fn >> 1][(fn & 1) + 2] };
                uint32_t bl_[2] = { kl[fn >> 1][(fn & 1) + 0], kl[fn >> 1][(fn & 1) + 2] };
                mma16816(sc[fn], ah, bh_);
                mma16816(sc[fn], al, bh_);
                mma16816(sc[fn], ah, bl_);
            }
        }

        // ---- Epilogue in registers: bias + silu/N + mask ----
        #pragma unroll
        for (int f = 0; f < 8; f++) {
            #pragma unroll
            for (int r = 0; r < 4; r++) {
                int il = row_lo + ((r >> 1) ? 8 : 0);
                int jl = f*8 + col_in + (r & 1);
                int ig = i0 + il, jg = j0 + jl;
                float s = sc[f][r] + pos_w[jg - ig + NSEQ - 1];
                int d = tsl[il] - tsj[jl];
                if (d < 0) d = -d;
                if (d < 1) d = 1;
                int bk = (int)(__logf((float)d) * 3.3222591f);
                bk = min(max(bk, 0), 64);
                s += tsw[bk];
                s = s / (1.0f + __expf(-s)) * (1.0f / NSEQ);
                if (jg > ig || pmj[jl]) s = 0.0f;
                sc[f][r] = s;
            }
        }

        // ---- Phase B: O += S @ V (3-term split; S packed from C-frags) ----
        const uint32_t svh = smem_to_u32(Vh), svl = smem_to_u32(Vl);
        #pragma unroll
        for (int ks = 0; ks < 4; ks++) {
            uint32_t ah[4], al[4];
            ah[0] = pack_hi(sc[2*ks][0],   sc[2*ks][1]);
            ah[1] = pack_hi(sc[2*ks][2],   sc[2*ks][3]);
            ah[2] = pack_hi(sc[2*ks+1][0], sc[2*ks+1][1]);
            ah[3] = pack_hi(sc[2*ks+1][2], sc[2*ks+1][3]);
            al[0] = pack_lo(sc[2*ks][0],   sc[2*ks][1],   ah[0]);
            al[1] = pack_lo(sc[2*ks][2],   sc[2*ks][3],   ah[1]);
            al[2] = pack_lo(sc[2*ks+1][0], sc[2*ks+1][1], ah[2]);
            al[3] = pack_lo(sc[2*ks+1][2], sc[2*ks+1][3], ah[3]);
            // V^T fragments via ldmatrix.trans:
            // addr row j = ks*16 + ((lane>>3)&1)*8 + (lane&7), col d = dg*16 + (lane>>4)*8
            uint32_t voff = ((ks*16 + ((lane >> 3) & 1)*8 + (lane & 7))*ATPAD
                            + (lane >> 4)*8) * 2;
            #pragma unroll
            for (int dg = 0; dg < 4; dg++) {
                uint32_t vh[4], vl[4];
                ldsm4t(vh, svh + voff + dg*16*2);
                ldsm4t(vl, svl + voff + dg*16*2);
                #pragma unroll
                for (int half = 0; half < 2; half++) {
                    int fd = dg*2 + half;
                    uint32_t bh_[2] = { vh[half*2], vh[half*2 + 1] };
                    uint32_t bl_[2] = { vl[half*2], vl[half*2 + 1] };
                    mma16816(of[fd], ah, bh_);
                    mma16816(of[fd], al, bh_);
                    mma16816(of[fd], ah, bl_);
                }
            }
        }
    }

    // ---- write O ----
    #pragma unroll
    for (int fd = 0; fd < 8; fd++) {
        #pragma unroll
        for (int half = 0; half < 2; half++) {
            int row = i0 + row_lo + half*8;
            int col = h*64 + fd*8 + col_in;
            float2 v = { of[fd][half*2], of[fd][half*2 + 1] };
            *(float2*)&g_ao[(size_t)(b*NSEQ + row)*DMODEL + col] = v;
        }
    }
}

// ---------------------------------------------------------------------------
// Launch
// ---------------------------------------------------------------------------
extern "C" void kernel_launch(void* const* d_in, const int* in_sizes, int n_in,
                              void* d_out, int out_size) {
    const float*          x      = (const float*)d_in[0];
    const int*            ts     = (const int*)d_in[1];     // int32 (JAX x64 off)
    /* d_in[2] = cm — analytic triu(k=1), unused */
    const unsigned char*  pm     = (const unsigned char*)d_in[3];
    const float*          uvqk   = (const float*)d_in[4];
    const float*          o_w    = (const float*)d_in[5];
    const float*          o_b    = (const float*)d_in[6];
    const float*          ln_x_w = (const float*)d_in[7];
    const float*          ln_x_b = (const float*)d_in[8];
    const float*          ln_a_w = (const float*)d_in[9];
    const float*          ln_a_b = (const float*)d_in[10];
    const float*          ts_w   = (const float*)d_in[11];
    const float*          pos_w  = (const float*)d_in[12];
    float*                out    = (float*)d_out;

    __nv_bfloat16 *p_uoh, *p_uol, *p_nxh, *p_nxl, *p_th, *p_tl;
    __nv_bfloat16 *p_B1h, *p_B1l, *p_B2h, *p_B2l;
    cudaGetSymbolAddress((void**)&p_uoh, g_uoh);
    cudaGetSymbolAddress((void**)&p_uol, g_uol);
    cudaGetSymbolAddress((void**)&p_nxh, g_nxh);
    cudaGetSymbolAddress((void**)&p_nxl, g_nxl);
    cudaGetSymbolAddress((void**)&p_th,  g_th);
    cudaGetSymbolAddress((void**)&p_tl,  g_tl);
    cudaGetSymbolAddress((void**)&p_B1h, g_B1h);
    cudaGetSymbolAddress((void**)&p_B1l, g_B1l);
    cudaGetSymbolAddress((void**)&p_B2h, g_B2h);
    cudaGetSymbolAddress((void**)&p_B2l, g_B2l);

    cudaFuncSetAttribute(mma_gemm<0>, cudaFuncAttributeMaxDynamicSharedMemorySize, SMEM_GEMM);
    cudaFuncSetAttribute(mma_gemm<1>, cudaFuncAttributeMaxDynamicSharedMemorySize, SMEM_GEMM);
    cudaFuncSetAttribute(attn_kernel, cudaFuncAttributeMaxDynamicSharedMemorySize, SMEM_ATTN);

    // 0. weight transpose+split
    tsplit_kernel<<<dim3(EOUT/32, DMODEL/32), dim3(32, 8)>>>(uvqk, p_B1h, p_B1l, DMODEL, EOUT);
    tsplit_kernel<<<dim3(DMODEL/32, DMODEL/32), dim3(32, 8)>>>(o_w, p_B2h, p_B2l, DMODEL, DMODEL);

    // 1. LN(x) -> bf16 hi/lo
    ln_x_kernel<<<ROWS, 256>>>(x, ln_x_w, ln_x_b);

    // 2. uvqk GEMM + silu -> hi/lo bf16
    mma_gemm<0><<<dim3(EOUT/128, ROWS/128), 256, SMEM_GEMM>>>(
        p_nxh, p_nxl, p_nxh, p_B1h, p_B1h, p_B1l,
        nullptr, p_uoh, p_uol, EOUT, nullptr, nullptr, nullptr);

    // 3. attention (HMMA)
    attn_kernel<<<dim3(NSEQ/64, NB*NH), 128, SMEM_ATTN>>>(ts, pm, ts_w, pos_w);

    // 4. t = u * LN(ao)
    ln_a_kernel<<<ROWS, 256>>>(ln_a_w, ln_a_b);

    // 5. y = t @ o_w + o_b + x (pm-masked)
    mma_gemm<1><<<dim3(DMODEL/128, ROWS/128), 256, SMEM_GEMM>>>(
        p_th, p_tl, p_th, p_B2h, p_B2h, p_B2l,
        out, nullptr, nullptr, DMODEL, o_b, x, pm);
}

// round 9
// speedup vs baseline: 2.4449x; 1.2925x over previous
#include <cuda_runtime.h>
#include <cuda_bf16.h>
#include <cstdint>
#include <math.h>

// Problem constants
#define NB     4
#define NSEQ   1024
#define DMODEL 512
#define NH     8
#define HD     64
#define EOUT   2048          // 2*H*Dv + 2*H*Dq
#define ROWS   (NB*NSEQ)     // 4096

// Single dynamic-smem symbol (typed via casts in each kernel)
extern __shared__ __align__(128) unsigned char dynsmem[];

// ---------------------------------------------------------------------------
// Scratch (allocation-free -> __device__ globals)
// ---------------------------------------------------------------------------
__device__ float g_ao0[ROWS*DMODEL];  // attention output (split 0)
__device__ float g_ao1[ROWS*DMODEL];  // attention output (split 1, rows i>=512)
__device__ float g_bias[(size_t)NB*NSEQ*NSEQ];                    // rel-bias, head-invariant
__device__ __nv_bfloat16 g_uoh[ROWS*EOUT], g_uol[ROWS*EOUT];      // silu(nx@uvqk) hi/lo
__device__ __nv_bfloat16 g_nxh[ROWS*DMODEL], g_nxl[ROWS*DMODEL];  // LN(x) hi/lo
__device__ __nv_bfloat16 g_th [ROWS*DMODEL], g_tl [ROWS*DMODEL];  // u*LN(ao) hi/lo
__device__ __nv_bfloat16 g_B1h[EOUT*DMODEL], g_B1l[EOUT*DMODEL];  // uvqk^T  [2048][512]
__device__ __nv_bfloat16 g_B2h[DMODEL*DMODEL], g_B2l[DMODEL*DMODEL]; // o_w^T [512][512]

// ---------------------------------------------------------------------------
// mma.sync helpers (sm_80-era PTX, legal on compute_103)
// ---------------------------------------------------------------------------
__device__ __forceinline__ uint32_t smem_to_u32(const void* p) {
    uint32_t a;
    asm("{ .reg .u64 t; cvta.to.shared.u64 t, %1; cvt.u32.u64 %0, t; }" : "=r"(a) : "l"(p));
    return a;
}
__device__ __forceinline__ void ldsm4(uint32_t* r, uint32_t addr) {
    asm volatile("ldmatrix.sync.aligned.m8n8.x4.shared.b16 {%0,%1,%2,%3}, [%4];"
        : "=r"(r[0]), "=r"(r[1]), "=r"(r[2]), "=r"(r[3]) : "r"(addr));
}
__device__ __forceinline__ void ldsm4t(uint32_t* r, uint32_t addr) {
    asm volatile("ldmatrix.sync.aligned.m8n8.x4.trans.shared.b16 {%0,%1,%2,%3}, [%4];"
        : "=r"(r[0]), "=r"(r[1]), "=r"(r[2]), "=r"(r[3]) : "r"(addr));
}
__device__ __forceinline__ void mma16816(float* c, const uint32_t* a, const uint32_t* b) {
    asm volatile("mma.sync.aligned.m16n8k16.row.col.f32.bf16.bf16.f32 "
        "{%0,%1,%2,%3}, {%4,%5,%6,%7}, {%8,%9}, {%0,%1,%2,%3};"
        : "+f"(c[0]), "+f"(c[1]), "+f"(c[2]), "+f"(c[3])
        : "r"(a[0]), "r"(a[1]), "r"(a[2]), "r"(a[3]), "r"(b[0]), "r"(b[1]));
}
__device__ __forceinline__ void cp16(uint32_t s, const void* g) {
    asm volatile("cp.async.cg.shared.global [%0], [%1], 16;" :: "r"(s), "l"(g));
}
#define CP_COMMIT() asm volatile("cp.async.commit_group;")
#define CP_WAIT(N)  asm volatile("cp.async.wait_group %0;" :: "n"(N))

__device__ __forceinline__ uint32_t pack_hi(float a, float b) {
    __nv_bfloat162 t = __floats2bfloat162_rn(a, b);
    return *(uint32_t*)&t;
}
__device__ __forceinline__ uint32_t pack_lo(float a, float b, uint32_t hi) {
    __nv_bfloat162 h = *(__nv_bfloat162*)&hi;
    __nv_bfloat162 t = __floats2bfloat162_rn(a - __bfloat162float(h.x),
                                             b - __bfloat162float(h.y));
    return *(uint32_t*)&t;
}

// ---------------------------------------------------------------------------
// Block reduction (256 threads)
// ---------------------------------------------------------------------------
__device__ __forceinline__ float blk_reduce_sum(float v, float* sm) {
    int tid = threadIdx.x;
    #pragma unroll
    for (int o = 16; o > 0; o >>= 1) v += __shfl_down_sync(0xffffffffu, v, o);
    if ((tid & 31) == 0) sm[tid >> 5] = v;
    __syncthreads();
    if (tid < 32) {
        float t = (tid < 8) ? sm[tid] : 0.0f;
        #pragma unroll
        for (int o = 4; o > 0; o >>= 1) t += __shfl_down_sync(0xffffffffu, t, o);
        if (tid == 0) sm[0] = t;
    }
    __syncthreads();
    float r = sm[0];
    __syncthreads();
    return r;
}

__device__ __forceinline__ void split_write(__nv_bfloat16* ph, __nv_bfloat16* pl,
                                            size_t idx, float v) {
    __nv_bfloat16 h = __float2bfloat16(v);
    ph[idx] = h;
    pl[idx] = __float2bfloat16(v - __bfloat162float(h));
}

// ---------------------------------------------------------------------------
// Kernel: relative bias precompute.  grid=4096 (b*1024+i), block=256 (4 j each)
// bias[b][i][j] = pos_w[j-i+N-1] + ts_w[bucket(|ts[i+1]-ts[j]|)]
// ---------------------------------------------------------------------------
__global__ void bias_kernel(const int* __restrict__ ts,
                            const float* __restrict__ tw,
                            const float* __restrict__ pw) {
    int bi = blockIdx.x, b = bi >> 10, i = bi & 1023;
    int j = threadIdx.x * 4;
    int ip = i + 1; if (ip > NSEQ - 1) ip = NSEQ - 1;
    int tl = ts[(b << 10) + ip];
    int4 tj = *(const int4*)&ts[(b << 10) + j];
    float4 o;
    {
        int d = tl - tj.x; if (d < 0) d = -d; if (d < 1) d = 1;
        int bk = (int)(__logf((float)d) * 3.3222591f);
        bk = min(max(bk, 0), 64);
        o.x = pw[j - i + NSEQ - 1] + tw[bk];
    }
    {
        int d = tl - tj.y; if (d < 0) d = -d; if (d < 1) d = 1;
        int bk = (int)(__logf((float)d) * 3.3222591f);
        bk = min(max(bk, 0), 64);
        o.y = pw[j + 1 - i + NSEQ - 1] + tw[bk];
    }
    {
        int d = tl - tj.z; if (d < 0) d = -d; if (d < 1) d = 1;
        int bk = (int)(__logf((float)d) * 3.3222591f);
        bk = min(max(bk, 0), 64);
        o.z = pw[j + 2 - i + NSEQ - 1] + tw[bk];
    }
    {
        int d = tl - tj.w; if (d < 0) d = -d; if (d < 1) d = 1;
        int bk = (int)(__logf((float)d) * 3.3222591f);
        bk = min(max(bk, 0), 64);
        o.w = pw[j + 3 - i + NSEQ - 1] + tw[bk];
    }
    *(float4*)&g_bias[((size_t)(b << 10) + i) * NSEQ + j] = o;
}

// ---------------------------------------------------------------------------
// Kernel 1: LayerNorm(x) -> g_nxh/g_nxl          grid=4096, block=256
// ---------------------------------------------------------------------------
__global__ void ln_x_kernel(const float* __restrict__ x,
                            const float* __restrict__ w,
                            const float* __restrict__ b) {
    __shared__ float sm[8];
    int r = blockIdx.x, tid = threadIdx.x;
    const float* xr = x + (size_t)r * DMODEL;
    float v0 = xr[tid], v1 = xr[tid + 256];
    float mean = blk_reduce_sum(v0 + v1, sm) * (1.0f / DMODEL);
    float d0 = v0 - mean, d1 = v1 - mean;
    float var = blk_reduce_sum(d0*d0 + d1*d1, sm) * (1.0f / DMODEL);
    float inv = rsqrtf(var + 1e-5f);
    split_write(g_nxh, g_nxl, (size_t)r*DMODEL + tid,       d0*inv*w[tid]       + b[tid]);
    split_write(g_nxh, g_nxl, (size_t)r*DMODEL + tid + 256, d1*inv*w[tid + 256] + b[tid + 256]);
}

// ---------------------------------------------------------------------------
// Kernel 4: t = u * LayerNorm(ao0 [+ ao1])  -> g_th/g_tl   grid=4096, block=256
// ---------------------------------------------------------------------------
__global__ void ln_a_kernel(const float* __restrict__ w,
                            const float* __restrict__ b) {
    __shared__ float sm[8];
    int r = blockIdx.x, tid = threadIdx.x;
    const bool two = (r & 1023) >= 512;        // rows from split query tiles
    size_t base = (size_t)r * DMODEL;
    float v0 = g_ao0[base + tid], v1 = g_ao0[base + tid + 256];
    if (two) { v0 += g_ao1[base + tid]; v1 += g_ao1[base + tid + 256]; }
    float mean = blk_reduce_sum(v0 + v1, sm) * (1.0f / DMODEL);
    float d0 = v0 - mean, d1 = v1 - mean;
    float var = blk_reduce_sum(d0*d0 + d1*d1, sm) * (1.0f / DMODEL);
    float inv = rsqrtf(var + 1e-5f);
    size_t ub = (size_t)r * EOUT;
    float u0 = __bfloat162float(g_uoh[ub + tid])       + __bfloat162float(g_uol[ub + tid]);
    float u1 = __bfloat162float(g_uoh[ub + tid + 256]) + __bfloat162float(g_uol[ub + tid + 256]);
    split_write(g_th, g_tl, base + tid,       (d0*inv*w[tid]       + b[tid])       * u0);
    split_write(g_th, g_tl, base + tid + 256, (d1*inv*w[tid + 256] + b[tid + 256]) * u1);
}

// ---------------------------------------------------------------------------
// Transpose + bf16 split: in[K][N] fp32 -> oh/ol[N][K] bf16
// ---------------------------------------------------------------------------
__global__ void tsplit_kernel(const float* __restrict__ in,
                              __nv_bfloat16* __restrict__ oh,
                              __nv_bfloat16* __restrict__ ol,
                              int K, int N) {
    __shared__ float tile[32][33];
    int n0 = blockIdx.x * 32, k0 = blockIdx.y * 32;
    int tx = threadIdx.x, ty = threadIdx.y;
    #pragma unroll
    for (int i = 0; i < 4; i++)
        tile[ty + i*8][tx] = in[(size_t)(k0 + ty + i*8) * N + n0 + tx];
    __syncthreads();
    #pragma unroll
    for (int i = 0; i < 4; i++) {
        float v = tile[tx][ty + i*8];
        __nv_bfloat16 h = __float2bfloat16(v);
        size_t o = (size_t)(n0 + ty + i*8) * K + k0 + tx;
        oh[o] = h;
        ol[o] = __float2bfloat16(v - __bfloat162float(h));
    }
}

// ---------------------------------------------------------------------------
// 3-stage cp.async bf16-split GEMM (HMMA).
// C[M,N] = sum of Aseg @ Bseg^T over 3 (hi/lo) segment pairs.
// CTA 128x128, 8 warps (2m x 4n), warp 64x32, K chunks of 64, 1 sync/chunk.
// EPI 0: silu -> write hi/lo bf16 to Ch/Cl.  EPI 1: fp32 +bias+resid, pm mask.
// ---------------------------------------------------------------------------
#define KSEG   512
#define NCHUNK 24
#define SPAD   72
#define GSTAGE (2*128*SPAD*2)        // bytes per stage (A tile + B tile)
#define SMEM_GEMM (3*GSTAGE)

template<int EPI>
__global__ void __launch_bounds__(256)
mma_gemm(const __nv_bfloat16* __restrict__ A0, const __nv_bfloat16* __restrict__ A1,
         const __nv_bfloat16* __restrict__ A2,
         const __nv_bfloat16* __restrict__ B0, const __nv_bfloat16* __restrict__ B1,
         const __nv_bfloat16* __restrict__ B2,
         float* __restrict__ C,
         __nv_bfloat16* __restrict__ Ch, __nv_bfloat16* __restrict__ Cl, int N,
         const float* __restrict__ bias, const float* __restrict__ resid,
         const unsigned char* __restrict__ pm) {
    const int tid = threadIdx.x, wid = tid >> 5, lane = tid & 31;
    const int bm = blockIdx.y * 128, bn = blockIdx.x * 128;
    const int wm = wid & 1, wn = wid >> 1;

    const __nv_bfloat16* Aseg[3] = {A0, A1, A2};
    const __nv_bfloat16* Bseg[3] = {B0, B1, B2};

    const uint32_t sbase = smem_to_u32(dynsmem);
    const int lrow = lane & 15, lcol = (lane >> 4) * 8;
    const int crow = tid >> 3, ccol = (tid & 7) * 8;   // cp.async coords (32 rows/pass)

    float acc[4][4][4];
    #pragma unroll
    for (int i = 0; i < 4; i++)
        #pragma unroll
        for (int j = 0; j < 4; j++)
            #pragma unroll
            for (int k = 0; k < 4; k++) acc[i][j][k] = 0.0f;

    auto issue = [&](int c, int stg) {
        const __nv_bfloat16* Ab = Aseg[c >> 3];
        const __nv_bfloat16* Bb = Bseg[c >> 3];
        const int kc = (c & 7) * 64;
        const uint32_t st = sbase + stg * GSTAGE;
        #pragma unroll
        for (int i = 0; i < 4; i++) {
            int row = crow + i*32;
            cp16(st + (row*SPAD + ccol)*2,
                 Ab + (size_t)(bm + row)*KSEG + kc + ccol);
            cp16(st + (128*SPAD + row*SPAD + ccol)*2,
                 Bb + (size_t)(bn + row)*KSEG + kc + ccol);
        }
        CP_COMMIT();
    };

    issue(0, 0);
    issue(1, 1);
    int stg = 0;
    for (int c = 0; c < NCHUNK; c++) {
        if (c + 1 < NCHUNK) { CP_WAIT(1); } else { CP_WAIT(0); }
        __syncthreads();
        if (c + 2 < NCHUNK) {
            int ns = stg + 2; if (ns >= 3) ns -= 3;
            issue(c + 2, ns);
        }
        const uint32_t sa = sbase + stg * GSTAGE;
        const uint32_t sb = sa + 128*SPAD*2;
        #pragma unroll
        for (int ks = 0; ks < 4; ks++) {
            uint32_t af[4][4], bf[2][4];
            #pragma unroll
            for (int fm = 0; fm < 4; fm++)
                ldsm4(af[fm], sa + ((wm*64 + fm*16 + lrow)*SPAD + ks*16 + lcol)*2);
            #pragma unroll
            for (int g = 0; g < 2; g++)
                ldsm4(bf[g], sb + ((wn*32 + g*16 + lrow)*SPAD + ks*16 + lcol)*2);
            #pragma unroll
            for (int fm = 0; fm < 4; fm++)
                #pragma unroll
                for (int fn = 0; fn < 4; fn++) {
                    uint32_t bb[2] = { bf[fn >> 1][(fn & 1) + 0],
                                       bf[fn >> 1][(fn & 1) + 2] };
                    mma16816(acc[fm][fn], af[fm], bb);
                }
        }
        if (++stg == 3) stg = 0;
    }

    #pragma unroll
    for (int fm = 0; fm < 4; fm++) {
        #pragma unroll
        for (int half = 0; half < 2; half++) {
            int r = bm + wm*64 + fm*16 + (lane >> 2) + half*8;
            #pragma unroll
            for (int fn = 0; fn < 4; fn++) {
                int cc = bn + wn*32 + fn*8 + (lane & 3)*2;
                float vx = acc[fm][fn][half*2 + 0];
                float vy = acc[fm][fn][half*2 + 1];
                if (EPI == 0) {
                    vx = vx / (1.0f + __expf(-vx));
                    vy = vy / (1.0f + __expf(-vy));
                    uint32_t hi = pack_hi(vx, vy);
                    uint32_t lo = pack_lo(vx, vy, hi);
                    *(uint32_t*)&Ch[(size_t)r*N + cc] = hi;
                    *(uint32_t*)&Cl[(size_t)r*N + cc] = lo;
                } else {
                    vx += bias[cc]     + resid[(size_t)r*N + cc];
                    vy += bias[cc + 1] + resid[(size_t)r*N + cc + 1];
                    if (pm[r]) { vx = 0.0f; vy = 0.0f; }
                    float2 v = {vx, vy};
                    *(float2*)&C[(size_t)r*N + cc] = v;
                }
            }
        }
    }
}

// ---------------------------------------------------------------------------
// Kernel 3: causal silu-attention (HMMA) with precomputed bias.
// grid (32 bh, 24 work), block 128.  Work mapping (big-first):
//   wy<16:  it = 15-(wy>>1), split half (wy&1): j in [0,m) -> ao0, [m,it+1) -> ao1
//   wy>=16: it = 23-wy (7..0), full range -> ao0
// ---------------------------------------------------------------------------
#define ATPAD 72
#define ATILE (64*ATPAD*2)           // 9216 B per bf16 tile
#define ATT_QH 0
#define ATT_QL (1*ATILE)
#define ATT_KH (2*ATILE)
#define ATT_KL (3*ATILE)
#define ATT_VH (4*ATILE)
#define ATT_VL (5*ATILE)
#define ATT_PM (6*ATILE)
#define SMEM_ATTN (ATT_PM + 64*4)

__global__ void __launch_bounds__(128)
attn_kernel(const unsigned char* __restrict__ pm) {
    unsigned char* sm = dynsmem;
    __nv_bfloat16* Qh = (__nv_bfloat16*)(sm + ATT_QH);
    __nv_bfloat16* Ql = (__nv_bfloat16*)(sm + ATT_QL);
    int* pmj = (int*)(sm + ATT_PM);

    const int bh = blockIdx.x, b = bh >> 3, h = bh & 7;
    const int wy = blockIdx.y;
    int it, jlo, jhi, dst;
    if (wy < 16) {
        it = 15 - (wy >> 1);
        int m = (it + 2) >> 1;
        if (wy & 1) { jlo = m; jhi = it + 1; dst = 1; }
        else        { jlo = 0; jhi = m;      dst = 0; }
    } else {
        it = 23 - wy; jlo = 0; jhi = it + 1; dst = 0;
    }
    const int i0 = it * 64;
    const int tid = threadIdx.x, wq = tid >> 5, lane = tid & 31;
    const int lrow = lane & 15, lcol = (lane >> 4) * 8;

    const uint32_t sqh = smem_to_u32(Qh), sql = smem_to_u32(Ql);
    const uint32_t skh = sqh + (ATT_KH - ATT_QH), skl = sqh + (ATT_KL - ATT_QH);
    const uint32_t svh = sqh + (ATT_VH - ATT_QH), svl = sqh + (ATT_VL - ATT_QH);

    // Q tiles (cols 1024 + h*64) via cp.async
    #pragma unroll
    for (int i = 0; i < 4; i++) {
        int id = i*128 + tid, row = id >> 3, col = (id & 7) * 8;
        size_t src = (size_t)(b*NSEQ + i0 + row)*EOUT + 1024 + h*64 + col;
        cp16(sqh + (row*ATPAD + col)*2, &g_uoh[src]);
        cp16(sql + (row*ATPAD + col)*2, &g_uol[src]);
    }
    CP_COMMIT(); CP_WAIT(0);
    __syncthreads();

    float of[8][4];
    #pragma unroll
    for (int f = 0; f < 8; f++)
        #pragma unroll
        for (int r = 0; r < 4; r++) of[f][r] = 0.0f;

    const int row_lo = wq*16 + (lane >> 2);
    const int col_in = (lane & 3) * 2;

    for (int jt = jlo; jt < jhi; jt++) {
        const int j0 = jt * 64;
        __syncthreads();   // protect K/V from previous iteration's phase B
        #pragma unroll
        for (int i = 0; i < 4; i++) {
            int id = i*128 + tid, row = id >> 3, col = (id & 7) * 8;
            size_t bkv = (size_t)(b*NSEQ + j0 + row)*EOUT + h*64 + col;
            cp16(skh + (row*ATPAD + col)*2, &g_uoh[bkv + 1536]);
            cp16(skl + (row*ATPAD + col)*2, &g_uol[bkv + 1536]);
            cp16(svh + (row*ATPAD + col)*2, &g_uoh[bkv + 512]);
            cp16(svl + (row*ATPAD + col)*2, &g_uol[bkv + 512]);
        }
        if (tid < 64) pmj[tid] = pm[b*NSEQ + j0 + tid];
        CP_COMMIT(); CP_WAIT(0);
        __syncthreads();

        // ---- Phase A: S = Q K^T (3-term split) ----
        float sc[8][4];
        #pragma unroll
        for (int f = 0; f < 8; f++)
            #pragma unroll
            for (int r = 0; r < 4; r++) sc[f][r] = 0.0f;

        #pragma unroll
        for (int ks = 0; ks < 4; ks++) {
            uint32_t ah[4], al[4], kh[4][4], kl[4][4];
            ldsm4(ah, sqh + ((wq*16 + lrow)*ATPAD + ks*16 + lcol)*2);
            ldsm4(al, sql + ((wq*16 + lrow)*ATPAD + ks*16 + lcol)*2);
            #pragma unroll
            for (int g = 0; g < 4; g++) {
                ldsm4(kh[g], skh + ((g*16 + lrow)*ATPAD + ks*16 + lcol)*2);
                ldsm4(kl[g], skl + ((g*16 + lrow)*ATPAD + ks*16 + lcol)*2);
            }
            #pragma unroll
            for (int fn = 0; fn < 8; fn++) {
                uint32_t bh_[2] = { kh[fn >> 1][(fn & 1) + 0], kh[fn >> 1][(fn & 1) + 2] };
                uint32_t bl_[2] = { kl[fn >> 1][(fn & 1) + 0], kl[fn >> 1][(fn & 1) + 2] };
                mma16816(sc[fn], ah, bh_);
                mma16816(sc[fn], al, bh_);
                mma16816(sc[fn], ah, bl_);
            }
        }

        // ---- Epilogue: +bias (precomputed), silu/N, mask ----
        #pragma unroll
        for (int f = 0; f < 8; f++) {
            int jb = j0 + f*8 + col_in;
            float2 b0 = *(const float2*)&g_bias[((size_t)(b << 10) + i0 + row_lo)     * NSEQ + jb];
            float2 b1 = *(const float2*)&g_bias[((size_t)(b << 10) + i0 + row_lo + 8) * NSEQ + jb];
            #pragma unroll
            for (int r = 0; r < 4; r++) {
                int il = row_lo + ((r >> 1) ? 8 : 0);
                int jl = f*8 + col_in + (r & 1);
                int ig = i0 + il, jg = j0 + jl;
                float bb = (r < 2) ? ((r & 1) ? b0.y : b0.x) : ((r & 1) ? b1.y : b1.x);
                float s = sc[f][r] + bb;
                s = s / (1.0f + __expf(-s)) * (1.0f / NSEQ);
                if (jg > ig || pmj[jl]) s = 0.0f;
                sc[f][r] = s;
            }
        }

        // ---- Phase B: O += S @ V (3-term split; S packed from C-frags) ----
        #pragma unroll
        for (int ks = 0; ks < 4; ks++) {
            uint32_t ah[4], al[4];
            ah[0] = pack_hi(sc[2*ks][0],   sc[2*ks][1]);
            ah[1] = pack_hi(sc[2*ks][2],   sc[2*ks][3]);
            ah[2] = pack_hi(sc[2*ks+1][0], sc[2*ks+1][1]);
            ah[3] = pack_hi(sc[2*ks+1][2], sc[2*ks+1][3]);
            al[0] = pack_lo(sc[2*ks][0],   sc[2*ks][1],   ah[0]);
            al[1] = pack_lo(sc[2*ks][2],   sc[2*ks][3],   ah[1]);
            al[2] = pack_lo(sc[2*ks+1][0], sc[2*ks+1][1], ah[2]);
            al[3] = pack_lo(sc[2*ks+1][2], sc[2*ks+1][3], ah[3]);
            uint32_t voff = ((ks*16 + ((lane >> 3) & 1)*8 + (lane & 7))*ATPAD
                            + (lane >> 4)*8) * 2;
            #pragma unroll
            for (int dg = 0; dg < 4; dg++) {
                uint32_t vh[4], vl[4];
                ldsm4t(vh, svh + voff + dg*16*2);
                ldsm4t(vl, svl + voff + dg*16*2);
                #pragma unroll
                for (int half = 0; half < 2; half++) {
                    int fd = dg*2 + half;
                    uint32_t bh_[2] = { vh[half*2], vh[half*2 + 1] };
                    uint32_t bl_[2] = { vl[half*2], vl[half*2 + 1] };
                    mma16816(of[fd], ah, bh_);
                    mma16816(of[fd], al, bh_);
                    mma16816(of[fd], ah, bl_);
                }
            }
        }
    }

    // ---- write O partial ----
    float* aop = dst ? g_ao1 : g_ao0;
    #pragma unroll
    for (int fd = 0; fd < 8; fd++) {
        #pragma unroll
        for (int half = 0; half < 2; half++) {
            int row = i0 + row_lo + half*8;
            int col = h*64 + fd*8 + col_in;
            float2 v = { of[fd][half*2], of[fd][half*2 + 1] };
            *(float2*)&aop[(size_t)(b*NSEQ + row)*DMODEL + col] = v;
        }
    }
}

// ---------------------------------------------------------------------------
// Launch
// ---------------------------------------------------------------------------
extern "C" void kernel_launch(void* const* d_in, const int* in_sizes, int n_in,
                              void* d_out, int out_size) {
    const float*          x      = (const float*)d_in[0];
    const int*            ts     = (const int*)d_in[1];     // int32 (JAX x64 off)
    /* d_in[2] = cm — analytic triu(k=1), unused */
    const unsigned char*  pm     = (const unsigned char*)d_in[3];
    const float*          uvqk   = (const float*)d_in[4];
    const float*          o_w    = (const float*)d_in[5];
    const float*          o_b    = (const float*)d_in[6];
    const float*          ln_x_w = (const float*)d_in[7];
    const float*          ln_x_b = (const float*)d_in[8];
    const float*          ln_a_w = (const float*)d_in[9];
    const float*          ln_a_b = (const float*)d_in[10];
    const float*          ts_w   = (const float*)d_in[11];
    const float*          pos_w  = (const float*)d_in[12];
    float*                out    = (float*)d_out;

    __nv_bfloat16 *p_uoh, *p_uol, *p_nxh, *p_nxl, *p_th, *p_tl;
    __nv_bfloat16 *p_B1h, *p_B1l, *p_B2h, *p_B2l;
    cudaGetSymbolAddress((void**)&p_uoh, g_uoh);
    cudaGetSymbolAddress((void**)&p_uol, g_uol);
    cudaGetSymbolAddress((void**)&p_nxh, g_nxh);
    cudaGetSymbolAddress((void**)&p_nxl, g_nxl);
    cudaGetSymbolAddress((void**)&p_th,  g_th);
    cudaGetSymbolAddress((void**)&p_tl,  g_tl);
    cudaGetSymbolAddress((void**)&p_B1h, g_B1h);
    cudaGetSymbolAddress((void**)&p_B1l, g_B1l);
    cudaGetSymbolAddress((void**)&p_B2h, g_B2h);
    cudaGetSymbolAddress((void**)&p_B2l, g_B2l);

    cudaFuncSetAttribute(mma_gemm<0>, cudaFuncAttributeMaxDynamicSharedMemorySize, SMEM_GEMM);
    cudaFuncSetAttribute(mma_gemm<1>, cudaFuncAttributeMaxDynamicSharedMemorySize, SMEM_GEMM);
    cudaFuncSetAttribute(attn_kernel, cudaFuncAttributeMaxDynamicSharedMemorySize, SMEM_ATTN);

    // 0. weight transpose+split, bias precompute
    tsplit_kernel<<<dim3(EOUT/32, DMODEL/32), dim3(32, 8)>>>(uvqk, p_B1h, p_B1l, DMODEL, EOUT);
    tsplit_kernel<<<dim3(DMODEL/32, DMODEL/32), dim3(32, 8)>>>(o_w, p_B2h, p_B2l, DMODEL, DMODEL);
    bias_kernel<<<NB*NSEQ, 256>>>(ts, ts_w, pos_w);

    // 1. LN(x) -> bf16 hi/lo
    ln_x_kernel<<<ROWS, 256>>>(x, ln_x_w, ln_x_b);

    // 2. uvqk GEMM + silu -> hi/lo bf16
    mma_gemm<0><<<dim3(EOUT/128, ROWS/128), 256, SMEM_GEMM>>>(
        p_nxh, p_nxl, p_nxh, p_B1h, p_B1h, p_B1l,
        nullptr, p_uoh, p_uol, EOUT, nullptr, nullptr, nullptr);

    // 3. attention (HMMA, split long query tiles)
    attn_kernel<<<dim3(NB*NH, 24), 128, SMEM_ATTN>>>(pm);

    // 4. t = u * LN(ao)
    ln_a_kernel<<<ROWS, 256>>>(ln_a_w, ln_a_b);

    // 5. y = t @ o_w + o_b + x (pm-masked)
    mma_gemm<1><<<dim3(DMODEL/128, ROWS/128), 256, SMEM_GEMM>>>(
        p_th, p_tl, p_th, p_B2h, p_B2h, p_B2l,
        out, nullptr, nullptr, DMODEL, o_b, x, pm);
}